// round 8
// baseline (speedup 1.0000x reference)
#include <cuda_runtime.h>
#include <cstdint>
#include <cstddef>

#define NU 100000
#define NI 200000
#define BB 3
#define EE 1000000
#define DD 64
#define CAP 64   // bucket capacity per row (Poisson(10) tail: P(>=64) ~ 1e-28)

// Scratch (device globals: allocation-free per harness rules)
__device__ float g_uscr[(size_t)BB * NU * DD];     // 76.8 MB  pre-GEMM user scratch
__device__ float g_iscr[(size_t)BB * NI * DD];     // 153.6 MB pre-GEMM item scratch
__device__ uint2 g_bucket_u[(size_t)NU * CAP];     // 51.2 MB  (val,col) per user row
__device__ uint2 g_bucket_i[(size_t)NI * CAP];     // 102.4 MB (val,col) per item row
__device__ int   g_cnt_u[NU];
__device__ int   g_cnt_i[NI];

// ---------------------------------------------------------------------------
// Phase 1: bucket edges by destination row.
// ---------------------------------------------------------------------------
__global__ void __launch_bounds__(256) bucket_scatter(
    const float* __restrict__ vals,
    const int*   __restrict__ rows,
    const int*   __restrict__ cols,
    int*         __restrict__ cnt,
    uint2*       __restrict__ buf,
    int nE)
{
    int e = blockIdx.x * blockDim.x + threadIdx.x;
    if (e >= nE) return;
    float v = vals[e];
    int   r = rows[e];
    int   c = cols[e];
    int slot = atomicAdd(&cnt[r], 1);
    if (slot < CAP)
        buf[(size_t)r * CAP + slot] = make_uint2(__float_as_uint(v), (unsigned)c);
}

// ---------------------------------------------------------------------------
// Phase 2: CSR-style gather. One warp per output row; register accumulation;
// single plain 256B store (also zeroes empty rows -> no scratch memset).
// 2-edge software pipeline for MLP.
// ---------------------------------------------------------------------------
__global__ void __launch_bounds__(256) csr_gather(
    const int*   __restrict__ cnt,
    const uint2* __restrict__ buf,
    const float* __restrict__ dense,   // [n_cols, 64]
    float*       __restrict__ out,     // [N, 64]
    int N)
{
    int warp = (blockIdx.x * blockDim.x + threadIdx.x) >> 5;
    int lane = threadIdx.x & 31;
    if (warp >= N) return;

    int n = cnt[warp];
    n = n < CAP ? n : CAP;

    const uint2*  eb = buf + (size_t)warp * CAP;
    const float2* d2 = reinterpret_cast<const float2*>(dense);

    float2 acc = make_float2(0.0f, 0.0f);
    int j = 0;
    for (; j + 2 <= n; j += 2) {
        uint2 e0 = __ldg(&eb[j]);
        uint2 e1 = __ldg(&eb[j + 1]);
        float2 a = __ldg(&d2[(size_t)e0.y * 32 + lane]);
        float2 b = __ldg(&d2[(size_t)e1.y * 32 + lane]);
        float v0 = __uint_as_float(e0.x);
        float v1 = __uint_as_float(e1.x);
        acc.x = fmaf(v0, a.x, acc.x);
        acc.y = fmaf(v0, a.y, acc.y);
        acc.x = fmaf(v1, b.x, acc.x);
        acc.y = fmaf(v1, b.y, acc.y);
    }
    if (j < n) {
        uint2 e0 = __ldg(&eb[j]);
        float2 a = __ldg(&d2[(size_t)e0.y * 32 + lane]);
        float v0 = __uint_as_float(e0.x);
        acc.x = fmaf(v0, a.x, acc.x);
        acc.y = fmaf(v0, a.y, acc.y);
    }
    reinterpret_cast<float2*>(out)[(size_t)warp * 32 + lane] = acc;
}

// ---------------------------------------------------------------------------
// tf32 tensor-core GEMM + sigmoid + in-register behavior mean (R7, unchanged).
// ---------------------------------------------------------------------------
__device__ __forceinline__ float sigmoidf_(float x) {
    return 1.0f / (1.0f + __expf(-x));
}
__device__ __forceinline__ uint32_t to_tf32(float x) {
    uint32_t v;
    asm("cvt.rna.tf32.f32 %0, %1;" : "=r"(v) : "f"(x));
    return v;
}
#define MMA_TF32(c0,c1,c2,c3, a0,a1,a2,a3, b0,b1)                            \
    asm volatile("mma.sync.aligned.m16n8k8.row.col.f32.tf32.tf32.f32 "       \
        "{%0,%1,%2,%3}, {%4,%5,%6,%7}, {%8,%9}, {%0,%1,%2,%3};"              \
        : "+f"(c0), "+f"(c1), "+f"(c2), "+f"(c3)                             \
        : "r"(a0), "r"(a1), "r"(a2), "r"(a3), "r"(b0), "r"(b1))

#define XSTRIDE 68

__global__ void __launch_bounds__(256) gemm_sig_mma(
    const float* __restrict__ scr,      // [3, N, 64]
    const float* __restrict__ W,        // [64, 64] row-major (k, n)
    float*       __restrict__ out_per,  // [3, N, 64]
    float*       __restrict__ out_mean, // [N, 64]
    int N)
{
    __shared__ uint32_t sW[64 * 72];
    __shared__ uint32_t sX[3 * 64 * XSTRIDE];

    int t  = threadIdx.x;
    int n0 = blockIdx.x * 64;

    #pragma unroll
    for (int i = 0; i < 16; i++) {
        int j = t + i * 256;
        sW[(j >> 6) * 72 + (j & 63)] = to_tf32(W[j]);
    }

    const float4* scr4 = reinterpret_cast<const float4*>(scr);
    #pragma unroll
    for (int i = 0; i < 12; i++) {
        int u  = t + i * 256;
        int rb = u >> 4;
        int kq = u & 15;
        int b  = rb >> 6;
        int r  = rb & 63;
        float4 x = make_float4(0.f, 0.f, 0.f, 0.f);
        if (n0 + r < N)
            x = scr4[((size_t)b * N + n0 + r) * 16 + kq];
        uint4 xt;
        xt.x = to_tf32(x.x); xt.y = to_tf32(x.y);
        xt.z = to_tf32(x.z); xt.w = to_tf32(x.w);
        *reinterpret_cast<uint4*>(&sX[rb * XSTRIDE + kq * 4]) = xt;
    }
    __syncthreads();

    int warp = t >> 5, lane = t & 31;
    int gid = lane >> 2, tig = lane & 3;
    int mt = warp & 3, nh = warp >> 2;

    int r0l = mt * 16 + gid;
    int r1l = r0l + 8;
    int r0  = n0 + r0l;
    int r1  = n0 + r1l;
    bool p0 = r0 < N, p1 = r1 < N;

    float acc[3][4][4];
    #pragma unroll
    for (int b = 0; b < 3; b++)
        #pragma unroll
        for (int nt = 0; nt < 4; nt++)
            #pragma unroll
            for (int q = 0; q < 4; q++) acc[b][nt][q] = 0.0f;

    #pragma unroll
    for (int ks = 0; ks < 8; ks++) {
        int k0 = ks * 8;
        uint32_t bf[4][2];
        #pragma unroll
        for (int nt = 0; nt < 4; nt++) {
            int col = nh * 32 + nt * 8 + gid;
            bf[nt][0] = sW[(k0 + tig) * 72 + col];
            bf[nt][1] = sW[(k0 + tig + 4) * 72 + col];
        }
        #pragma unroll
        for (int b = 0; b < 3; b++) {
            const uint32_t* xb = sX + b * 64 * XSTRIDE;
            uint32_t a0 = xb[r0l * XSTRIDE + k0 + tig];
            uint32_t a1 = xb[r1l * XSTRIDE + k0 + tig];
            uint32_t a2 = xb[r0l * XSTRIDE + k0 + tig + 4];
            uint32_t a3 = xb[r1l * XSTRIDE + k0 + tig + 4];
            #pragma unroll
            for (int nt = 0; nt < 4; nt++)
                MMA_TF32(acc[b][nt][0], acc[b][nt][1], acc[b][nt][2], acc[b][nt][3],
                         a0, a1, a2, a3, bf[nt][0], bf[nt][1]);
        }
    }

    const float third = 1.0f / 3.0f;
    #pragma unroll
    for (int nt = 0; nt < 4; nt++) {
        int c0 = nh * 32 + nt * 8 + 2 * tig;
        float m0 = 0.0f, m1 = 0.0f, m2 = 0.0f, m3 = 0.0f;
        #pragma unroll
        for (int b = 0; b < 3; b++) {
            float y0 = acc[b][nt][0], y1 = acc[b][nt][1];
            float y2 = acc[b][nt][2], y3 = acc[b][nt][3];
            m0 += y0; m1 += y1; m2 += y2; m3 += y3;
            if (p0) *reinterpret_cast<float2*>(out_per + ((size_t)b * N + r0) * 64 + c0)
                        = make_float2(sigmoidf_(y0), sigmoidf_(y1));
            if (p1) *reinterpret_cast<float2*>(out_per + ((size_t)b * N + r1) * 64 + c0)
                        = make_float2(sigmoidf_(y2), sigmoidf_(y3));
        }
        if (p0) *reinterpret_cast<float2*>(out_mean + (size_t)r0 * 64 + c0)
                    = make_float2(sigmoidf_(m0 * third), sigmoidf_(m1 * third));
        if (p1) *reinterpret_cast<float2*>(out_mean + (size_t)r1 * 64 + c0)
                    = make_float2(sigmoidf_(m2 * third), sigmoidf_(m3 * third));
    }
}

// ---------------------------------------------------------------------------
// Lazy stream/event creation (first call = correctness run, outside capture).
// ---------------------------------------------------------------------------
static cudaStream_t side_stream() {
    static cudaStream_t s = nullptr;
    if (!s) cudaStreamCreateWithFlags(&s, cudaStreamNonBlocking);
    return s;
}
static cudaEvent_t ev(int i) {
    static cudaEvent_t e[2] = {nullptr, nullptr};
    if (!e[i]) cudaEventCreateWithFlags(&e[i], cudaEventDisableTiming);
    return e[i];
}

// ---------------------------------------------------------------------------
// Launch DAG:
//   stream0: 3x [memset cnt_i -> bucket_i -> gather_i] -> (e_i2u)
//            3x [memset cnt_u -> bucket_u -> gather_u] -> gemm_u -> join
//   s1:      (wait e_i2u) gemm_i
// No scratch memsets: csr_gather writes every row.
// ---------------------------------------------------------------------------
extern "C" void kernel_launch(void* const* d_in, const int* in_sizes, int n_in,
                              void* d_out, int out_size)
{
    const float* user_emb = (const float*)d_in[0];
    const float* item_emb = (const float*)d_in[1];
    const float* u2i_vals = (const float*)d_in[2];
    const int*   u2i_rows = (const int*)  d_in[3];
    const int*   u2i_cols = (const int*)  d_in[4];
    const float* i2u_vals = (const float*)d_in[5];
    const int*   i2u_rows = (const int*)  d_in[6];
    const int*   i2u_cols = (const int*)  d_in[7];
    const float* u_w      = (const float*)d_in[8];
    const float* i_w      = (const float*)d_in[9];

    float* out     = (float*)d_out;
    float* out_ue  = out;                                                 // [NU,64]
    float* out_ie  = out + (size_t)NU * DD;                               // [NI,64]
    float* out_ues = out + (size_t)(NU + NI) * DD;                        // [3,NU,64]
    float* out_ies = out + (size_t)(NU + NI) * DD + (size_t)BB * NU * DD; // [3,NI,64]

    void* p;
    cudaGetSymbolAddress(&p, g_uscr);     float* uscr   = (float*)p;
    cudaGetSymbolAddress(&p, g_iscr);     float* iscr   = (float*)p;
    cudaGetSymbolAddress(&p, g_bucket_u); uint2* buf_u  = (uint2*)p;
    cudaGetSymbolAddress(&p, g_bucket_i); uint2* buf_i  = (uint2*)p;
    cudaGetSymbolAddress(&p, g_cnt_u);    int*   cnt_u  = (int*)p;
    cudaGetSymbolAddress(&p, g_cnt_i);    int*   cnt_i  = (int*)p;

    cudaStream_t s1 = side_stream();
    cudaEvent_t e_i2u = ev(0), e_join = ev(1);

    const int EGRID = (EE + 255) / 256;

    // ---- item side: 3 behaviors (rows in NI, gather from user_emb) ----
    for (int b = 0; b < BB; b++) {
        cudaMemsetAsync(cnt_i, 0, NI * sizeof(int), 0);
        bucket_scatter<<<EGRID, 256>>>(
            i2u_vals + (size_t)b * EE, i2u_rows + (size_t)b * EE,
            i2u_cols + (size_t)b * EE, cnt_i, buf_i, EE);
        csr_gather<<<(NI * 32 + 255) / 256, 256>>>(
            cnt_i, buf_i, user_emb, iscr + (size_t)b * NI * DD, NI);
    }
    cudaEventRecord(e_i2u, 0);

    // s1: item GEMM, overlaps the user-side chain below
    cudaStreamWaitEvent(s1, e_i2u, 0);
    gemm_sig_mma<<<(NI + 63) / 64, 256, 0, s1>>>(iscr, i_w, out_ies, out_ie, NI);
    cudaEventRecord(e_join, s1);

    // ---- user side: 3 behaviors (rows in NU, gather from item_emb) ----
    for (int b = 0; b < BB; b++) {
        cudaMemsetAsync(cnt_u, 0, NU * sizeof(int), 0);
        bucket_scatter<<<EGRID, 256>>>(
            u2i_vals + (size_t)b * EE, u2i_rows + (size_t)b * EE,
            u2i_cols + (size_t)b * EE, cnt_u, buf_u, EE);
        csr_gather<<<(NU * 32 + 255) / 256, 256>>>(
            cnt_u, buf_u, item_emb, uscr + (size_t)b * NU * DD, NU);
    }
    gemm_sig_mma<<<(NU + 63) / 64, 256>>>(uscr, u_w, out_ues, out_ue, NU);

    cudaStreamWaitEvent(0, e_join, 0);
}

// round 9
// speedup vs baseline: 1.1144x; 1.1144x over previous
#include <cuda_runtime.h>
#include <cstdint>
#include <cstddef>

#define NU 100000
#define NI 200000
#define BB 3
#define EE 1000000
#define DD 64

// Scratch accumulators (device globals: allocation-free per harness rules)
__device__ float g_uscr[(size_t)BB * NU * DD];   // 76.8 MB
__device__ float g_iscr[(size_t)BB * NI * DD];   // 153.6 MB

// ---------------------------------------------------------------------------
// Scatter: COO spmm  out[row] += val * dense[col]  (red.global.add.v4.f32)
// R1/R7 kernel: 46.9us each at the LTS cap when run solo.
// ---------------------------------------------------------------------------
__global__ void __launch_bounds__(256) scatter_kernel(
    const float* __restrict__ vals,
    const int*   __restrict__ rows,
    const int*   __restrict__ cols,
    const float* __restrict__ dense,
    float*       __restrict__ out,
    int nE)
{
    int lane   = threadIdx.x & 31;
    int warpId = (blockIdx.x * blockDim.x + threadIdx.x) >> 5;
    int nWarps = (gridDim.x * blockDim.x) >> 5;
    int half   = lane >> 4;
    int l4     = lane & 15;

    for (int base = warpId * 32; base < nE; base += nWarps * 32) {
        int e = base + lane;
        float v = 0.0f; int r = 0, c = 0;
        if (e < nE) { v = vals[e]; r = rows[e]; c = cols[e]; }

        #pragma unroll
        for (int i = 0; i < 16; i++) {
            int src = 2 * i + half;
            float vv = __shfl_sync(0xffffffffu, v, src);
            int   rr = __shfl_sync(0xffffffffu, r, src);
            int   cc = __shfl_sync(0xffffffffu, c, src);

            const float4* dp = reinterpret_cast<const float4*>(dense + (size_t)cc * DD) + l4;
            float4 d = __ldg(dp);
            float4 p;
            p.x = vv * d.x; p.y = vv * d.y; p.z = vv * d.z; p.w = vv * d.w;

            float* op = out + (size_t)rr * DD + (size_t)l4 * 4;
            asm volatile("red.global.add.v4.f32 [%0], {%1,%2,%3,%4};"
                         :: "l"(op), "f"(p.x), "f"(p.y), "f"(p.z), "f"(p.w)
                         : "memory");
        }
    }
}

// ---------------------------------------------------------------------------
// tf32 tensor-core GEMM + sigmoid + in-register behavior mean, smem-staged.
// X staged as RAW fp32 bits (mma truncates low mantissa -> tf32 RZ on A side);
// W converted with cvt.rna (accuracy on B side). Stride 68 -> conflict-free.
// ---------------------------------------------------------------------------
__device__ __forceinline__ float sigmoidf_(float x) {
    return 1.0f / (1.0f + __expf(-x));
}
__device__ __forceinline__ uint32_t to_tf32(float x) {
    uint32_t v;
    asm("cvt.rna.tf32.f32 %0, %1;" : "=r"(v) : "f"(x));
    return v;
}
#define MMA_TF32(c0,c1,c2,c3, a0,a1,a2,a3, b0,b1)                            \
    asm volatile("mma.sync.aligned.m16n8k8.row.col.f32.tf32.tf32.f32 "       \
        "{%0,%1,%2,%3}, {%4,%5,%6,%7}, {%8,%9}, {%0,%1,%2,%3};"              \
        : "+f"(c0), "+f"(c1), "+f"(c2), "+f"(c3)                             \
        : "r"(a0), "r"(a1), "r"(a2), "r"(a3), "r"(b0), "r"(b1))

#define XSTRIDE 68

__global__ void __launch_bounds__(256) gemm_sig_mma(
    const float* __restrict__ scr,      // [3, N, 64]
    const float* __restrict__ W,        // [64, 64] row-major (k, n)
    float*       __restrict__ out_per,  // [3, N, 64]
    float*       __restrict__ out_mean, // [N, 64]
    int N)
{
    __shared__ uint32_t sW[64 * 72];
    __shared__ uint32_t sX[3 * 64 * XSTRIDE];

    int t  = threadIdx.x;
    int n0 = blockIdx.x * 64;

    #pragma unroll
    for (int i = 0; i < 16; i++) {
        int j = t + i * 256;
        sW[(j >> 6) * 72 + (j & 63)] = to_tf32(W[j]);
    }

    // Stage X: raw fp32 bits, no cvt (hardware truncation == tf32 RZ)
    const uint4* scr4 = reinterpret_cast<const uint4*>(scr);
    #pragma unroll
    for (int i = 0; i < 12; i++) {
        int u  = t + i * 256;           // 0..3071
        int rb = u >> 4;                // 0..191
        int kq = u & 15;
        int b  = rb >> 6;
        int r  = rb & 63;
        uint4 x = make_uint4(0u, 0u, 0u, 0u);
        if (n0 + r < N)
            x = scr4[((size_t)b * N + n0 + r) * 16 + kq];
        *reinterpret_cast<uint4*>(&sX[rb * XSTRIDE + kq * 4]) = x;
    }
    __syncthreads();

    int warp = t >> 5, lane = t & 31;
    int gid = lane >> 2, tig = lane & 3;
    int mt = warp & 3, nh = warp >> 2;

    int r0l = mt * 16 + gid;
    int r1l = r0l + 8;
    int r0  = n0 + r0l;
    int r1  = n0 + r1l;
    bool p0 = r0 < N, p1 = r1 < N;

    float acc[3][4][4];
    #pragma unroll
    for (int b = 0; b < 3; b++)
        #pragma unroll
        for (int nt = 0; nt < 4; nt++)
            #pragma unroll
            for (int q = 0; q < 4; q++) acc[b][nt][q] = 0.0f;

    #pragma unroll
    for (int ks = 0; ks < 8; ks++) {
        int k0 = ks * 8;
        uint32_t bf[4][2];
        #pragma unroll
        for (int nt = 0; nt < 4; nt++) {
            int col = nh * 32 + nt * 8 + gid;
            bf[nt][0] = sW[(k0 + tig) * 72 + col];
            bf[nt][1] = sW[(k0 + tig + 4) * 72 + col];
        }
        #pragma unroll
        for (int b = 0; b < 3; b++) {
            const uint32_t* xb = sX + b * 64 * XSTRIDE;
            uint32_t a0 = xb[r0l * XSTRIDE + k0 + tig];
            uint32_t a1 = xb[r1l * XSTRIDE + k0 + tig];
            uint32_t a2 = xb[r0l * XSTRIDE + k0 + tig + 4];
            uint32_t a3 = xb[r1l * XSTRIDE + k0 + tig + 4];
            #pragma unroll
            for (int nt = 0; nt < 4; nt++)
                MMA_TF32(acc[b][nt][0], acc[b][nt][1], acc[b][nt][2], acc[b][nt][3],
                         a0, a1, a2, a3, bf[nt][0], bf[nt][1]);
        }
    }

    const float third = 1.0f / 3.0f;
    #pragma unroll
    for (int nt = 0; nt < 4; nt++) {
        int c0 = nh * 32 + nt * 8 + 2 * tig;
        float m0 = 0.0f, m1 = 0.0f, m2 = 0.0f, m3 = 0.0f;
        #pragma unroll
        for (int b = 0; b < 3; b++) {
            float y0 = acc[b][nt][0], y1 = acc[b][nt][1];
            float y2 = acc[b][nt][2], y3 = acc[b][nt][3];
            m0 += y0; m1 += y1; m2 += y2; m3 += y3;
            if (p0) *reinterpret_cast<float2*>(out_per + ((size_t)b * N + r0) * 64 + c0)
                        = make_float2(sigmoidf_(y0), sigmoidf_(y1));
            if (p1) *reinterpret_cast<float2*>(out_per + ((size_t)b * N + r1) * 64 + c0)
                        = make_float2(sigmoidf_(y2), sigmoidf_(y3));
        }
        if (p0) *reinterpret_cast<float2*>(out_mean + (size_t)r0 * 64 + c0)
                    = make_float2(sigmoidf_(m0 * third), sigmoidf_(m1 * third));
        if (p1) *reinterpret_cast<float2*>(out_mean + (size_t)r1 * 64 + c0)
                    = make_float2(sigmoidf_(m2 * third), sigmoidf_(m3 * third));
    }
}

// ---------------------------------------------------------------------------
// Lazy stream/event creation (first call = correctness run, outside capture).
// ---------------------------------------------------------------------------
static cudaStream_t side_stream() {
    static cudaStream_t s = nullptr;
    if (!s) cudaStreamCreateWithFlags(&s, cudaStreamNonBlocking);
    return s;
}
static cudaEvent_t ev(int i) {
    static cudaEvent_t e[4] = {nullptr, nullptr, nullptr, nullptr};
    if (!e[i]) cudaEventCreateWithFlags(&e[i], cudaEventDisableTiming);
    return e[i];
}

// ---------------------------------------------------------------------------
// Launch DAG:
//   stream0: memset_i -> i2u x3 -> u2i x3 -> (e_all) -> gemm_u -> join
//   s1:      memset_u -> (wait e_all) gemm_i          [gemm||gemm only]
// Scatters run solo (no L2 contention); only the two DRAM-bound gemms overlap.
// ---------------------------------------------------------------------------
extern "C" void kernel_launch(void* const* d_in, const int* in_sizes, int n_in,
                              void* d_out, int out_size)
{
    const float* user_emb = (const float*)d_in[0];
    const float* item_emb = (const float*)d_in[1];
    const float* u2i_vals = (const float*)d_in[2];
    const int*   u2i_rows = (const int*)  d_in[3];
    const int*   u2i_cols = (const int*)  d_in[4];
    const float* i2u_vals = (const float*)d_in[5];
    const int*   i2u_rows = (const int*)  d_in[6];
    const int*   i2u_cols = (const int*)  d_in[7];
    const float* u_w      = (const float*)d_in[8];
    const float* i_w      = (const float*)d_in[9];

    float* out     = (float*)d_out;
    float* out_ue  = out;                                                 // [NU,64]
    float* out_ie  = out + (size_t)NU * DD;                               // [NI,64]
    float* out_ues = out + (size_t)(NU + NI) * DD;                        // [3,NU,64]
    float* out_ies = out + (size_t)(NU + NI) * DD + (size_t)BB * NU * DD; // [3,NI,64]

    void* p;
    cudaGetSymbolAddress(&p, g_uscr); float* uscr = (float*)p;
    cudaGetSymbolAddress(&p, g_iscr); float* iscr = (float*)p;

    cudaStream_t s1 = side_stream();
    cudaEvent_t e_fork = ev(0), e_mu = ev(1), e_all = ev(2), e_join = ev(3);

    cudaEventRecord(e_fork, 0);
    cudaStreamWaitEvent(s1, e_fork, 0);

    // parallel memsets
    cudaMemsetAsync(uscr, 0, sizeof(g_uscr), s1);
    cudaEventRecord(e_mu, s1);
    cudaMemsetAsync(iscr, 0, sizeof(g_iscr), 0);

    const int FULL_GRID = (EE + 255) / 256;

    // all 6 scatters solo on stream0 (each at the LTS cap)
    for (int b = 0; b < BB; b++) {
        scatter_kernel<<<FULL_GRID, 256>>>(
            i2u_vals + (size_t)b * EE, i2u_rows + (size_t)b * EE,
            i2u_cols + (size_t)b * EE, user_emb,
            iscr + (size_t)b * NI * DD, EE);
    }
    cudaStreamWaitEvent(0, e_mu, 0);
    for (int b = 0; b < BB; b++) {
        scatter_kernel<<<FULL_GRID, 256>>>(
            u2i_vals + (size_t)b * EE, u2i_rows + (size_t)b * EE,
            u2i_cols + (size_t)b * EE, item_emb,
            uscr + (size_t)b * NU * DD, EE);
    }
    cudaEventRecord(e_all, 0);

    // the two DRAM-bound gemms run concurrently
    cudaStreamWaitEvent(s1, e_all, 0);
    gemm_sig_mma<<<(NI + 63) / 64, 256, 0, s1>>>(iscr, i_w, out_ies, out_ie, NI);
    cudaEventRecord(e_join, s1);

    gemm_sig_mma<<<(NU + 63) / 64, 256>>>(uscr, u_w, out_ues, out_ue, NU);

    cudaStreamWaitEvent(0, e_join, 0);
}

// round 10
// speedup vs baseline: 1.1168x; 1.0021x over previous
#include <cuda_runtime.h>
#include <cuda_fp16.h>
#include <cstdint>
#include <cstddef>

#define NU 100000
#define NI 200000
#define BB 3
#define EE 1000000
#define DD 64

// Scratch (device globals: allocation-free per harness rules)
__device__ float  g_uscr[(size_t)BB * NU * DD];   // 76.8 MB
__device__ float  g_iscr[(size_t)BB * NI * DD];   // 153.6 MB
__device__ __half g_emb16_u[(size_t)NU * DD];     // 12.8 MB fp16 user table
__device__ __half g_emb16_i[(size_t)NI * DD];     // 25.6 MB fp16 item table

// ---------------------------------------------------------------------------
// fp32 -> fp16 table conversion (coalesced float4 -> 2x half2)
// ---------------------------------------------------------------------------
__global__ void __launch_bounds__(256) f32_to_f16(
    const float4* __restrict__ in, __half2* __restrict__ out, int n4)
{
    int i = blockIdx.x * blockDim.x + threadIdx.x;
    if (i >= n4) return;
    float4 v = __ldg(&in[i]);
    out[2 * i]     = __floats2half2_rn(v.x, v.y);
    out[2 * i + 1] = __floats2half2_rn(v.z, v.w);
}

// ---------------------------------------------------------------------------
// Scatter: COO spmm  out[row] += val * dense16[col]  (red.global.add.v4.f32)
// fp16 gather (128B/row: lane l4 loads 8B = 4 halves), fp32 atomics.
// ---------------------------------------------------------------------------
__global__ void __launch_bounds__(256) scatter_kernel(
    const float*  __restrict__ vals,
    const int*    __restrict__ rows,
    const int*    __restrict__ cols,
    const __half* __restrict__ dense,   // [n_cols, 64] fp16
    float*        __restrict__ out,     // [N, 64] fp32
    int nE)
{
    int lane   = threadIdx.x & 31;
    int warpId = (blockIdx.x * blockDim.x + threadIdx.x) >> 5;
    int nWarps = (gridDim.x * blockDim.x) >> 5;
    int half_  = lane >> 4;
    int l4     = lane & 15;

    for (int base = warpId * 32; base < nE; base += nWarps * 32) {
        int e = base + lane;
        float v = 0.0f; int r = 0, c = 0;
        if (e < nE) { v = vals[e]; r = rows[e]; c = cols[e]; }

        #pragma unroll
        for (int i = 0; i < 16; i++) {
            int src = 2 * i + half_;
            float vv = __shfl_sync(0xffffffffu, v, src);
            int   rr = __shfl_sync(0xffffffffu, r, src);
            int   cc = __shfl_sync(0xffffffffu, c, src);

            const uint2* dp = reinterpret_cast<const uint2*>(dense + (size_t)cc * DD) + l4;
            uint2 raw = __ldg(dp);
            __half2 h0 = *reinterpret_cast<__half2*>(&raw.x);
            __half2 h1 = *reinterpret_cast<__half2*>(&raw.y);
            float2 f0 = __half22float2(h0);
            float2 f1 = __half22float2(h1);

            float4 p;
            p.x = vv * f0.x; p.y = vv * f0.y; p.z = vv * f1.x; p.w = vv * f1.y;

            float* op = out + (size_t)rr * DD + (size_t)l4 * 4;
            asm volatile("red.global.add.v4.f32 [%0], {%1,%2,%3,%4};"
                         :: "l"(op), "f"(p.x), "f"(p.y), "f"(p.z), "f"(p.w)
                         : "memory");
        }
    }
}

// ---------------------------------------------------------------------------
// tf32 tensor-core GEMM + sigmoid + in-register behavior mean (R9, unchanged).
// ---------------------------------------------------------------------------
__device__ __forceinline__ float sigmoidf_(float x) {
    return 1.0f / (1.0f + __expf(-x));
}
__device__ __forceinline__ uint32_t to_tf32(float x) {
    uint32_t v;
    asm("cvt.rna.tf32.f32 %0, %1;" : "=r"(v) : "f"(x));
    return v;
}
#define MMA_TF32(c0,c1,c2,c3, a0,a1,a2,a3, b0,b1)                            \
    asm volatile("mma.sync.aligned.m16n8k8.row.col.f32.tf32.tf32.f32 "       \
        "{%0,%1,%2,%3}, {%4,%5,%6,%7}, {%8,%9}, {%0,%1,%2,%3};"              \
        : "+f"(c0), "+f"(c1), "+f"(c2), "+f"(c3)                             \
        : "r"(a0), "r"(a1), "r"(a2), "r"(a3), "r"(b0), "r"(b1))

#define XSTRIDE 68

__global__ void __launch_bounds__(256) gemm_sig_mma(
    const float* __restrict__ scr,      // [3, N, 64]
    const float* __restrict__ W,        // [64, 64] row-major (k, n)
    float*       __restrict__ out_per,  // [3, N, 64]
    float*       __restrict__ out_mean, // [N, 64]
    int N)
{
    __shared__ uint32_t sW[64 * 72];
    __shared__ uint32_t sX[3 * 64 * XSTRIDE];

    int t  = threadIdx.x;
    int n0 = blockIdx.x * 64;

    #pragma unroll
    for (int i = 0; i < 16; i++) {
        int j = t + i * 256;
        sW[(j >> 6) * 72 + (j & 63)] = to_tf32(W[j]);
    }

    // Stage X: raw fp32 bits (mma truncates -> tf32 RZ on A side)
    const uint4* scr4 = reinterpret_cast<const uint4*>(scr);
    #pragma unroll
    for (int i = 0; i < 12; i++) {
        int u  = t + i * 256;
        int rb = u >> 4;
        int kq = u & 15;
        int b  = rb >> 6;
        int r  = rb & 63;
        uint4 x = make_uint4(0u, 0u, 0u, 0u);
        if (n0 + r < N)
            x = scr4[((size_t)b * N + n0 + r) * 16 + kq];
        *reinterpret_cast<uint4*>(&sX[rb * XSTRIDE + kq * 4]) = x;
    }
    __syncthreads();

    int warp = t >> 5, lane = t & 31;
    int gid = lane >> 2, tig = lane & 3;
    int mt = warp & 3, nh = warp >> 2;

    int r0l = mt * 16 + gid;
    int r1l = r0l + 8;
    int r0  = n0 + r0l;
    int r1  = n0 + r1l;
    bool p0 = r0 < N, p1 = r1 < N;

    float acc[3][4][4];
    #pragma unroll
    for (int b = 0; b < 3; b++)
        #pragma unroll
        for (int nt = 0; nt < 4; nt++)
            #pragma unroll
            for (int q = 0; q < 4; q++) acc[b][nt][q] = 0.0f;

    #pragma unroll
    for (int ks = 0; ks < 8; ks++) {
        int k0 = ks * 8;
        uint32_t bf[4][2];
        #pragma unroll
        for (int nt = 0; nt < 4; nt++) {
            int col = nh * 32 + nt * 8 + gid;
            bf[nt][0] = sW[(k0 + tig) * 72 + col];
            bf[nt][1] = sW[(k0 + tig + 4) * 72 + col];
        }
        #pragma unroll
        for (int b = 0; b < 3; b++) {
            const uint32_t* xb = sX + b * 64 * XSTRIDE;
            uint32_t a0 = xb[r0l * XSTRIDE + k0 + tig];
            uint32_t a1 = xb[r1l * XSTRIDE + k0 + tig];
            uint32_t a2 = xb[r0l * XSTRIDE + k0 + tig + 4];
            uint32_t a3 = xb[r1l * XSTRIDE + k0 + tig + 4];
            #pragma unroll
            for (int nt = 0; nt < 4; nt++)
                MMA_TF32(acc[b][nt][0], acc[b][nt][1], acc[b][nt][2], acc[b][nt][3],
                         a0, a1, a2, a3, bf[nt][0], bf[nt][1]);
        }
    }

    const float third = 1.0f / 3.0f;
    #pragma unroll
    for (int nt = 0; nt < 4; nt++) {
        int c0 = nh * 32 + nt * 8 + 2 * tig;
        float m0 = 0.0f, m1 = 0.0f, m2 = 0.0f, m3 = 0.0f;
        #pragma unroll
        for (int b = 0; b < 3; b++) {
            float y0 = acc[b][nt][0], y1 = acc[b][nt][1];
            float y2 = acc[b][nt][2], y3 = acc[b][nt][3];
            m0 += y0; m1 += y1; m2 += y2; m3 += y3;
            if (p0) *reinterpret_cast<float2*>(out_per + ((size_t)b * N + r0) * 64 + c0)
                        = make_float2(sigmoidf_(y0), sigmoidf_(y1));
            if (p1) *reinterpret_cast<float2*>(out_per + ((size_t)b * N + r1) * 64 + c0)
                        = make_float2(sigmoidf_(y2), sigmoidf_(y3));
        }
        if (p0) *reinterpret_cast<float2*>(out_mean + (size_t)r0 * 64 + c0)
                    = make_float2(sigmoidf_(m0 * third), sigmoidf_(m1 * third));
        if (p1) *reinterpret_cast<float2*>(out_mean + (size_t)r1 * 64 + c0)
                    = make_float2(sigmoidf_(m2 * third), sigmoidf_(m3 * third));
    }
}

// ---------------------------------------------------------------------------
// Lazy stream/event creation (first call = correctness run, outside capture).
// ---------------------------------------------------------------------------
static cudaStream_t side_stream() {
    static cudaStream_t s = nullptr;
    if (!s) cudaStreamCreateWithFlags(&s, cudaStreamNonBlocking);
    return s;
}
static cudaEvent_t ev(int i) {
    static cudaEvent_t e[5] = {nullptr, nullptr, nullptr, nullptr, nullptr};
    if (!e[i]) cudaEventCreateWithFlags(&e[i], cudaEventDisableTiming);
    return e[i];
}

// ---------------------------------------------------------------------------
// Launch DAG:
//   stream0: memset_i ──(wait cu)── i2u x3 ──(wait ui)── u2i x3 ── gemm_u ── join
//   s1:      convert_u (e_cu) ─ memset_u ─ convert_i (e_ui) ─ (wait all) gemm_i
// Conversions + memset_u hide under memset_i / i2u scatters (DRAM 75% idle).
// ---------------------------------------------------------------------------
extern "C" void kernel_launch(void* const* d_in, const int* in_sizes, int n_in,
                              void* d_out, int out_size)
{
    const float* user_emb = (const float*)d_in[0];
    const float* item_emb = (const float*)d_in[1];
    const float* u2i_vals = (const float*)d_in[2];
    const int*   u2i_rows = (const int*)  d_in[3];
    const int*   u2i_cols = (const int*)  d_in[4];
    const float* i2u_vals = (const float*)d_in[5];
    const int*   i2u_rows = (const int*)  d_in[6];
    const int*   i2u_cols = (const int*)  d_in[7];
    const float* u_w      = (const float*)d_in[8];
    const float* i_w      = (const float*)d_in[9];

    float* out     = (float*)d_out;
    float* out_ue  = out;                                                 // [NU,64]
    float* out_ie  = out + (size_t)NU * DD;                               // [NI,64]
    float* out_ues = out + (size_t)(NU + NI) * DD;                        // [3,NU,64]
    float* out_ies = out + (size_t)(NU + NI) * DD + (size_t)BB * NU * DD; // [3,NI,64]

    void* p;
    cudaGetSymbolAddress(&p, g_uscr);     float*  uscr   = (float*)p;
    cudaGetSymbolAddress(&p, g_iscr);     float*  iscr   = (float*)p;
    cudaGetSymbolAddress(&p, g_emb16_u);  __half* emb16u = (__half*)p;
    cudaGetSymbolAddress(&p, g_emb16_i);  __half* emb16i = (__half*)p;

    cudaStream_t s1 = side_stream();
    cudaEvent_t e_fork = ev(0), e_cu = ev(1), e_ui = ev(2), e_all = ev(3), e_join = ev(4);

    cudaEventRecord(e_fork, 0);
    cudaStreamWaitEvent(s1, e_fork, 0);

    // s1: convert user table (needed by i2u), then memset_u + convert item table
    f32_to_f16<<<(NU * 16 + 255) / 256, 256, 0, s1>>>(
        (const float4*)user_emb, (__half2*)emb16u, NU * 16);
    cudaEventRecord(e_cu, s1);
    cudaMemsetAsync(uscr, 0, sizeof(g_uscr), s1);
    f32_to_f16<<<(NI * 16 + 255) / 256, 256, 0, s1>>>(
        (const float4*)item_emb, (__half2*)emb16i, NI * 16);
    cudaEventRecord(e_ui, s1);

    // stream0: memset_i, then scatters
    cudaMemsetAsync(iscr, 0, sizeof(g_iscr), 0);

    const int FULL_GRID = (EE + 255) / 256;

    cudaStreamWaitEvent(0, e_cu, 0);
    for (int b = 0; b < BB; b++) {
        scatter_kernel<<<FULL_GRID, 256>>>(
            i2u_vals + (size_t)b * EE, i2u_rows + (size_t)b * EE,
            i2u_cols + (size_t)b * EE, emb16u,
            iscr + (size_t)b * NI * DD, EE);
    }
    cudaStreamWaitEvent(0, e_ui, 0);
    for (int b = 0; b < BB; b++) {
        scatter_kernel<<<FULL_GRID, 256>>>(
            u2i_vals + (size_t)b * EE, u2i_rows + (size_t)b * EE,
            u2i_cols + (size_t)b * EE, emb16i,
            uscr + (size_t)b * NU * DD, EE);
    }
    cudaEventRecord(e_all, 0);

    // gemms (item on s1, user on stream0)
    cudaStreamWaitEvent(s1, e_all, 0);
    gemm_sig_mma<<<(NI + 63) / 64, 256, 0, s1>>>(iscr, i_w, out_ies, out_ie, NI);
    cudaEventRecord(e_join, s1);

    gemm_sig_mma<<<(NU + 63) / 64, 256>>>(uscr, u_w, out_ues, out_ue, NU);

    cudaStreamWaitEvent(0, e_join, 0);
}

// round 11
// speedup vs baseline: 1.1184x; 1.0014x over previous
#include <cuda_runtime.h>
#include <cuda_fp16.h>
#include <cstdint>
#include <cstddef>

#define NU 100000
#define NI 200000
#define BB 3
#define EE 1000000
#define DD 64

// Scratch (device globals: allocation-free per harness rules)
__device__ float  g_uscr[(size_t)BB * NU * DD];   // 76.8 MB
__device__ float  g_iscr[(size_t)BB * NI * DD];   // 153.6 MB
__device__ __half g_emb16_u[(size_t)NU * DD];     // 12.8 MB fp16 user table
__device__ __half g_emb16_i[(size_t)NI * DD];     // 25.6 MB fp16 item table

// ---------------------------------------------------------------------------
// fp32 -> fp16 table conversion
// ---------------------------------------------------------------------------
__global__ void __launch_bounds__(256) f32_to_f16(
    const float4* __restrict__ in, __half2* __restrict__ out, int n4)
{
    int i = blockIdx.x * blockDim.x + threadIdx.x;
    if (i >= n4) return;
    float4 v = __ldg(&in[i]);
    out[2 * i]     = __floats2half2_rn(v.x, v.y);
    out[2 * i + 1] = __floats2half2_rn(v.z, v.w);
}

// ---------------------------------------------------------------------------
// Scatter: COO spmm  out[row] += val * dense16[col]  (red.global.add.v4.f32)
// ---------------------------------------------------------------------------
__global__ void __launch_bounds__(256) scatter_kernel(
    const float*  __restrict__ vals,
    const int*    __restrict__ rows,
    const int*    __restrict__ cols,
    const __half* __restrict__ dense,   // [n_cols, 64] fp16
    float*        __restrict__ out,     // [N, 64] fp32
    int nE)
{
    int lane   = threadIdx.x & 31;
    int warpId = (blockIdx.x * blockDim.x + threadIdx.x) >> 5;
    int nWarps = (gridDim.x * blockDim.x) >> 5;
    int half_  = lane >> 4;
    int l4     = lane & 15;

    for (int base = warpId * 32; base < nE; base += nWarps * 32) {
        int e = base + lane;
        float v = 0.0f; int r = 0, c = 0;
        if (e < nE) { v = vals[e]; r = rows[e]; c = cols[e]; }

        #pragma unroll
        for (int i = 0; i < 16; i++) {
            int src = 2 * i + half_;
            float vv = __shfl_sync(0xffffffffu, v, src);
            int   rr = __shfl_sync(0xffffffffu, r, src);
            int   cc = __shfl_sync(0xffffffffu, c, src);

            const uint2* dp = reinterpret_cast<const uint2*>(dense + (size_t)cc * DD) + l4;
            uint2 raw = __ldg(dp);
            __half2 h0 = *reinterpret_cast<__half2*>(&raw.x);
            __half2 h1 = *reinterpret_cast<__half2*>(&raw.y);
            float2 f0 = __half22float2(h0);
            float2 f1 = __half22float2(h1);

            float4 p;
            p.x = vv * f0.x; p.y = vv * f0.y; p.z = vv * f1.x; p.w = vv * f1.y;

            float* op = out + (size_t)rr * DD + (size_t)l4 * 4;
            asm volatile("red.global.add.v4.f32 [%0], {%1,%2,%3,%4};"
                         :: "l"(op), "f"(p.x), "f"(p.y), "f"(p.z), "f"(p.w)
                         : "memory");
        }
    }
}

// ---------------------------------------------------------------------------
// Fused dual tf32 tensor-core GEMM + sigmoid + behavior mean.
// One grid covers BOTH problems (user then item): blockIdx selects the
// problem, so the two DRAM-bound GEMMs co-schedule perfectly.
// ---------------------------------------------------------------------------
__device__ __forceinline__ float sigmoidf_(float x) {
    return 1.0f / (1.0f + __expf(-x));
}
__device__ __forceinline__ uint32_t to_tf32(float x) {
    uint32_t v;
    asm("cvt.rna.tf32.f32 %0, %1;" : "=r"(v) : "f"(x));
    return v;
}
#define MMA_TF32(c0,c1,c2,c3, a0,a1,a2,a3, b0,b1)                            \
    asm volatile("mma.sync.aligned.m16n8k8.row.col.f32.tf32.tf32.f32 "       \
        "{%0,%1,%2,%3}, {%4,%5,%6,%7}, {%8,%9}, {%0,%1,%2,%3};"              \
        : "+f"(c0), "+f"(c1), "+f"(c2), "+f"(c3)                             \
        : "r"(a0), "r"(a1), "r"(a2), "r"(a3), "r"(b0), "r"(b1))

#define XSTRIDE 68

__global__ void __launch_bounds__(256) gemm_sig_mma_dual(
    const float* __restrict__ scr_u,   const float* __restrict__ w_u,
    float* __restrict__ per_u,         float* __restrict__ mean_u,
    const float* __restrict__ scr_i,   const float* __restrict__ w_i,
    float* __restrict__ per_i,         float* __restrict__ mean_i,
    int nblk_u)
{
    __shared__ uint32_t sW[64 * 72];
    __shared__ uint32_t sX[3 * 64 * XSTRIDE];

    const float* scr;  const float* W;
    float* out_per;    float* out_mean;
    int N, blk;
    if ((int)blockIdx.x < nblk_u) {
        blk = blockIdx.x;
        scr = scr_u; W = w_u; out_per = per_u; out_mean = mean_u; N = NU;
    } else {
        blk = blockIdx.x - nblk_u;
        scr = scr_i; W = w_i; out_per = per_i; out_mean = mean_i; N = NI;
    }

    int t  = threadIdx.x;
    int n0 = blk * 64;

    #pragma unroll
    for (int i = 0; i < 16; i++) {
        int j = t + i * 256;
        sW[(j >> 6) * 72 + (j & 63)] = to_tf32(W[j]);
    }

    // Stage X: raw fp32 bits (mma truncates -> tf32 RZ on A side)
    const uint4* scr4 = reinterpret_cast<const uint4*>(scr);
    #pragma unroll
    for (int i = 0; i < 12; i++) {
        int u  = t + i * 256;
        int rb = u >> 4;
        int kq = u & 15;
        int b  = rb >> 6;
        int r  = rb & 63;
        uint4 x = make_uint4(0u, 0u, 0u, 0u);
        if (n0 + r < N)
            x = scr4[((size_t)b * N + n0 + r) * 16 + kq];
        *reinterpret_cast<uint4*>(&sX[rb * XSTRIDE + kq * 4]) = x;
    }
    __syncthreads();

    int warp = t >> 5, lane = t & 31;
    int gid = lane >> 2, tig = lane & 3;
    int mt = warp & 3, nh = warp >> 2;

    int r0l = mt * 16 + gid;
    int r1l = r0l + 8;
    int r0  = n0 + r0l;
    int r1  = n0 + r1l;
    bool p0 = r0 < N, p1 = r1 < N;

    float acc[3][4][4];
    #pragma unroll
    for (int b = 0; b < 3; b++)
        #pragma unroll
        for (int nt = 0; nt < 4; nt++)
            #pragma unroll
            for (int q = 0; q < 4; q++) acc[b][nt][q] = 0.0f;

    #pragma unroll
    for (int ks = 0; ks < 8; ks++) {
        int k0 = ks * 8;
        uint32_t bf[4][2];
        #pragma unroll
        for (int nt = 0; nt < 4; nt++) {
            int col = nh * 32 + nt * 8 + gid;
            bf[nt][0] = sW[(k0 + tig) * 72 + col];
            bf[nt][1] = sW[(k0 + tig + 4) * 72 + col];
        }
        #pragma unroll
        for (int b = 0; b < 3; b++) {
            const uint32_t* xb = sX + b * 64 * XSTRIDE;
            uint32_t a0 = xb[r0l * XSTRIDE + k0 + tig];
            uint32_t a1 = xb[r1l * XSTRIDE + k0 + tig];
            uint32_t a2 = xb[r0l * XSTRIDE + k0 + tig + 4];
            uint32_t a3 = xb[r1l * XSTRIDE + k0 + tig + 4];
            #pragma unroll
            for (int nt = 0; nt < 4; nt++)
                MMA_TF32(acc[b][nt][0], acc[b][nt][1], acc[b][nt][2], acc[b][nt][3],
                         a0, a1, a2, a3, bf[nt][0], bf[nt][1]);
        }
    }

    const float third = 1.0f / 3.0f;
    #pragma unroll
    for (int nt = 0; nt < 4; nt++) {
        int c0 = nh * 32 + nt * 8 + 2 * tig;
        float m0 = 0.0f, m1 = 0.0f, m2 = 0.0f, m3 = 0.0f;
        #pragma unroll
        for (int b = 0; b < 3; b++) {
            float y0 = acc[b][nt][0], y1 = acc[b][nt][1];
            float y2 = acc[b][nt][2], y3 = acc[b][nt][3];
            m0 += y0; m1 += y1; m2 += y2; m3 += y3;
            if (p0) *reinterpret_cast<float2*>(out_per + ((size_t)b * N + r0) * 64 + c0)
                        = make_float2(sigmoidf_(y0), sigmoidf_(y1));
            if (p1) *reinterpret_cast<float2*>(out_per + ((size_t)b * N + r1) * 64 + c0)
                        = make_float2(sigmoidf_(y2), sigmoidf_(y3));
        }
        if (p0) *reinterpret_cast<float2*>(out_mean + (size_t)r0 * 64 + c0)
                    = make_float2(sigmoidf_(m0 * third), sigmoidf_(m1 * third));
        if (p1) *reinterpret_cast<float2*>(out_mean + (size_t)r1 * 64 + c0)
                    = make_float2(sigmoidf_(m2 * third), sigmoidf_(m3 * third));
    }
}

// ---------------------------------------------------------------------------
// Lazy stream/event creation (first call = correctness run, outside capture).
// ---------------------------------------------------------------------------
static cudaStream_t side_stream() {
    static cudaStream_t s = nullptr;
    if (!s) cudaStreamCreateWithFlags(&s, cudaStreamNonBlocking);
    return s;
}
static cudaEvent_t ev(int i) {
    static cudaEvent_t e[8] = {};
    if (!e[i]) cudaEventCreateWithFlags(&e[i], cudaEventDisableTiming);
    return e[i];
}

// ---------------------------------------------------------------------------
// Launch DAG:
//   stream0: memset iscr[0] ─(wait cu)─ i2u[0] ─(wait s1,b)─ i2u[1,2]
//            ─(wait ui,mu)─ u2i x3 ─ fused dual gemm ─ join
//   s1:      convert_u (e_cu) ─ memset iscr[1] (e1) ─ memset iscr[2] (e2)
//            ─ memset uscr (e_mu) ─ convert_i (e_ui)
// Only iscr[0]'s memset (8us) stays on the critical path before scatters.
// ---------------------------------------------------------------------------
extern "C" void kernel_launch(void* const* d_in, const int* in_sizes, int n_in,
                              void* d_out, int out_size)
{
    const float* user_emb = (const float*)d_in[0];
    const float* item_emb = (const float*)d_in[1];
    const float* u2i_vals = (const float*)d_in[2];
    const int*   u2i_rows = (const int*)  d_in[3];
    const int*   u2i_cols = (const int*)  d_in[4];
    const float* i2u_vals = (const float*)d_in[5];
    const int*   i2u_rows = (const int*)  d_in[6];
    const int*   i2u_cols = (const int*)  d_in[7];
    const float* u_w      = (const float*)d_in[8];
    const float* i_w      = (const float*)d_in[9];

    float* out     = (float*)d_out;
    float* out_ue  = out;                                                 // [NU,64]
    float* out_ie  = out + (size_t)NU * DD;                               // [NI,64]
    float* out_ues = out + (size_t)(NU + NI) * DD;                        // [3,NU,64]
    float* out_ies = out + (size_t)(NU + NI) * DD + (size_t)BB * NU * DD; // [3,NI,64]

    void* p;
    cudaGetSymbolAddress(&p, g_uscr);     float*  uscr   = (float*)p;
    cudaGetSymbolAddress(&p, g_iscr);     float*  iscr   = (float*)p;
    cudaGetSymbolAddress(&p, g_emb16_u);  __half* emb16u = (__half*)p;
    cudaGetSymbolAddress(&p, g_emb16_i);  __half* emb16i = (__half*)p;

    cudaStream_t s1 = side_stream();
    cudaEvent_t e_fork = ev(0), e_cu = ev(1), e_s1 = ev(2), e_s2 = ev(3),
                e_mu = ev(4), e_ui = ev(5);

    const size_t ISLICE = (size_t)NI * DD * sizeof(float);

    cudaEventRecord(e_fork, 0);
    cudaStreamWaitEvent(s1, e_fork, 0);

    // s1: convert_u, memset iscr slices 1,2, memset uscr, convert_i
    f32_to_f16<<<(NU * 16 + 255) / 256, 256, 0, s1>>>(
        (const float4*)user_emb, (__half2*)emb16u, NU * 16);
    cudaEventRecord(e_cu, s1);
    cudaMemsetAsync((char*)iscr + ISLICE, 0, ISLICE, s1);
    cudaEventRecord(e_s1, s1);
    cudaMemsetAsync((char*)iscr + 2 * ISLICE, 0, ISLICE, s1);
    cudaEventRecord(e_s2, s1);
    cudaMemsetAsync(uscr, 0, sizeof(g_uscr), s1);
    cudaEventRecord(e_mu, s1);
    f32_to_f16<<<(NI * 16 + 255) / 256, 256, 0, s1>>>(
        (const float4*)item_emb, (__half2*)emb16i, NI * 16);
    cudaEventRecord(e_ui, s1);

    // stream0: memset iscr slice 0 only (8us on critical path)
    cudaMemsetAsync(iscr, 0, ISLICE, 0);

    const int FULL_GRID = (EE + 255) / 256;

    cudaStreamWaitEvent(0, e_cu, 0);
    scatter_kernel<<<FULL_GRID, 256>>>(
        i2u_vals, i2u_rows, i2u_cols, emb16u, iscr, EE);
    cudaStreamWaitEvent(0, e_s1, 0);
    scatter_kernel<<<FULL_GRID, 256>>>(
        i2u_vals + (size_t)EE, i2u_rows + (size_t)EE, i2u_cols + (size_t)EE,
        emb16u, iscr + (size_t)NI * DD, EE);
    cudaStreamWaitEvent(0, e_s2, 0);
    scatter_kernel<<<FULL_GRID, 256>>>(
        i2u_vals + 2 * (size_t)EE, i2u_rows + 2 * (size_t)EE, i2u_cols + 2 * (size_t)EE,
        emb16u, iscr + 2 * (size_t)NI * DD, EE);

    cudaStreamWaitEvent(0, e_mu, 0);
    cudaStreamWaitEvent(0, e_ui, 0);
    for (int b = 0; b < BB; b++) {
        scatter_kernel<<<FULL_GRID, 256>>>(
            u2i_vals + (size_t)b * EE, u2i_rows + (size_t)b * EE,
            u2i_cols + (size_t)b * EE, emb16i,
            uscr + (size_t)b * NU * DD, EE);
    }

    // fused dual GEMM: both problems in one grid
    const int NBLK_U = (NU + 63) / 64;
    const int NBLK_I = (NI + 63) / 64;
    gemm_sig_mma_dual<<<NBLK_U + NBLK_I, 256>>>(
        uscr, u_w, out_ues, out_ue,
        iscr, i_w, out_ies, out_ie,
        NBLK_U);
}

// round 13
// speedup vs baseline: 1.1657x; 1.0423x over previous
#include <cuda_runtime.h>
#include <cuda_fp16.h>
#include <cstdint>
#include <cstddef>

#define NU 100000
#define NI 200000
#define BB 3
#define EE 1000000
#define DD 64

// Scratch (device globals: allocation-free per harness rules)
__device__ float    g_uscr[(size_t)BB * NU * DD];   // 76.8 MB
__device__ float    g_iscr[(size_t)BB * NI * DD];   // 153.6 MB
__device__ __half   g_emb16_u[(size_t)NU * DD];     // 12.8 MB fp16 user table
__device__ __half   g_emb16_i[(size_t)NI * DD];     // 25.6 MB fp16 item table
__device__ uint32_t g_w32_u[DD * DD];               // tf32 u_w
__device__ uint32_t g_w32_i[DD * DD];               // tf32 i_w

// ---------------------------------------------------------------------------
// Conversions
// ---------------------------------------------------------------------------
__global__ void __launch_bounds__(256) f32_to_f16(
    const float4* __restrict__ in, __half2* __restrict__ out, int n4)
{
    int i = blockIdx.x * blockDim.x + threadIdx.x;
    if (i >= n4) return;
    float4 v = __ldg(&in[i]);
    out[2 * i]     = __floats2half2_rn(v.x, v.y);
    out[2 * i + 1] = __floats2half2_rn(v.z, v.w);
}

__device__ __forceinline__ uint32_t to_tf32(float x) {
    uint32_t v;
    asm("cvt.rna.tf32.f32 %0, %1;" : "=r"(v) : "f"(x));
    return v;
}

__global__ void __launch_bounds__(256) w_to_tf32(
    const float* __restrict__ w, uint32_t* __restrict__ out)
{
    int i = blockIdx.x * blockDim.x + threadIdx.x;
    if (i < DD * DD) out[i] = to_tf32(w[i]);
}

// ---------------------------------------------------------------------------
// Scatter: COO spmm  out[row] += val * dense16[col]  (red.global.add.v4.f32)
// ---------------------------------------------------------------------------
__global__ void __launch_bounds__(256) scatter_kernel(
    const float*  __restrict__ vals,
    const int*    __restrict__ rows,
    const int*    __restrict__ cols,
    const __half* __restrict__ dense,   // [n_cols, 64] fp16
    float*        __restrict__ out,     // [N, 64] fp32
    int nE)
{
    int lane   = threadIdx.x & 31;
    int warpId = (blockIdx.x * blockDim.x + threadIdx.x) >> 5;
    int nWarps = (gridDim.x * blockDim.x) >> 5;
    int half_  = lane >> 4;
    int l4     = lane & 15;

    for (int base = warpId * 32; base < nE; base += nWarps * 32) {
        int e = base + lane;
        float v = 0.0f; int r = 0, c = 0;
        if (e < nE) { v = vals[e]; r = rows[e]; c = cols[e]; }

        #pragma unroll
        for (int i = 0; i < 16; i++) {
            int src = 2 * i + half_;
            float vv = __shfl_sync(0xffffffffu, v, src);
            int   rr = __shfl_sync(0xffffffffu, r, src);
            int   cc = __shfl_sync(0xffffffffu, c, src);

            const uint2* dp = reinterpret_cast<const uint2*>(dense + (size_t)cc * DD) + l4;
            uint2 raw = __ldg(dp);
            __half2 h0 = *reinterpret_cast<__half2*>(&raw.x);
            __half2 h1 = *reinterpret_cast<__half2*>(&raw.y);
            float2 f0 = __half22float2(h0);
            float2 f1 = __half22float2(h1);

            float4 p;
            p.x = vv * f0.x; p.y = vv * f0.y; p.z = vv * f1.x; p.w = vv * f1.y;

            float* op = out + (size_t)rr * DD + (size_t)l4 * 4;
            asm volatile("red.global.add.v4.f32 [%0], {%1,%2,%3,%4};"
                         :: "l"(op), "f"(p.x), "f"(p.y), "f"(p.z), "f"(p.w)
                         : "memory");
        }
    }
}

// ---------------------------------------------------------------------------
// Fused dual tf32 GEMM + sigmoid + behavior mean. 32-row tiles, 100% occ.
// No W smem (tf32 W in global, L1-resident). No bounds predicates
// (NU, NI both divisible by 32). 8 warps = 2 m-tiles x 4 n-quarters.
// ---------------------------------------------------------------------------
__device__ __forceinline__ float sigmoidf_(float x) {
    return 1.0f / (1.0f + __expf(-x));
}
#define MMA_TF32(c0,c1,c2,c3, a0,a1,a2,a3, b0,b1)                            \
    asm volatile("mma.sync.aligned.m16n8k8.row.col.f32.tf32.tf32.f32 "       \
        "{%0,%1,%2,%3}, {%4,%5,%6,%7}, {%8,%9}, {%0,%1,%2,%3};"              \
        : "+f"(c0), "+f"(c1), "+f"(c2), "+f"(c3)                             \
        : "r"(a0), "r"(a1), "r"(a2), "r"(a3), "r"(b0), "r"(b1))

#define XSTRIDE 68

__global__ void __launch_bounds__(256, 4) gemm_sig_mma_dual(
    const float* __restrict__ scr_u,   const uint32_t* __restrict__ w32_u,
    float* __restrict__ per_u,         float* __restrict__ mean_u,
    const float* __restrict__ scr_i,   const uint32_t* __restrict__ w32_i,
    float* __restrict__ per_i,         float* __restrict__ mean_i,
    int nblk_u)
{
    __shared__ uint32_t sX[3 * 32 * XSTRIDE];   // 26.1 KB

    const float* scr;  const uint32_t* W32;
    float* out_per;    float* out_mean;
    int N, blk;
    if ((int)blockIdx.x < nblk_u) {
        blk = blockIdx.x;
        scr = scr_u; W32 = w32_u; out_per = per_u; out_mean = mean_u; N = NU;
    } else {
        blk = blockIdx.x - nblk_u;
        scr = scr_i; W32 = w32_i; out_per = per_i; out_mean = mean_i; N = NI;
    }

    int t  = threadIdx.x;
    int n0 = blk * 32;

    // Stage X: 96 rows x 16 uint4, 6 per thread, coalesced, no predicates
    const uint4* scr4 = reinterpret_cast<const uint4*>(scr);
    #pragma unroll
    for (int i = 0; i < 6; i++) {
        int u  = t + i * 256;           // 0..1535
        int rb = u >> 4;                // 0..95
        int kq = u & 15;
        int b  = rb >> 5;
        int r  = rb & 31;
        uint4 x = scr4[((size_t)b * N + n0 + r) * 16 + kq];
        *reinterpret_cast<uint4*>(&sX[rb * XSTRIDE + kq * 4]) = x;
    }
    __syncthreads();

    int warp = t >> 5, lane = t & 31;
    int gid = lane >> 2, tig = lane & 3;
    int mt = warp & 1;                  // m-tile (0,1)
    int nq = warp >> 1;                 // n-quarter (0..3) -> 16 cols

    int r0l = mt * 16 + gid;
    int r1l = r0l + 8;
    int r0  = n0 + r0l;
    int r1  = n0 + r1l;

    float acc[3][2][4];
    #pragma unroll
    for (int b = 0; b < 3; b++)
        #pragma unroll
        for (int nt = 0; nt < 2; nt++)
            #pragma unroll
            for (int q = 0; q < 4; q++) acc[b][nt][q] = 0.0f;

    #pragma unroll
    for (int ks = 0; ks < 8; ks++) {
        int k0 = ks * 8;
        uint32_t bf[2][2];
        #pragma unroll
        for (int nt = 0; nt < 2; nt++) {
            int col = nq * 16 + nt * 8 + gid;
            bf[nt][0] = __ldg(&W32[(k0 + tig) * 64 + col]);
            bf[nt][1] = __ldg(&W32[(k0 + tig + 4) * 64 + col]);
        }
        #pragma unroll
        for (int b = 0; b < 3; b++) {
            const uint32_t* xb = sX + b * 32 * XSTRIDE;
            uint32_t a0 = xb[r0l * XSTRIDE + k0 + tig];
            uint32_t a1 = xb[r1l * XSTRIDE + k0 + tig];
            uint32_t a2 = xb[r0l * XSTRIDE + k0 + tig + 4];
            uint32_t a3 = xb[r1l * XSTRIDE + k0 + tig + 4];
            #pragma unroll
            for (int nt = 0; nt < 2; nt++)
                MMA_TF32(acc[b][nt][0], acc[b][nt][1], acc[b][nt][2], acc[b][nt][3],
                         a0, a1, a2, a3, bf[nt][0], bf[nt][1]);
        }
    }

    const float third = 1.0f / 3.0f;
    #pragma unroll
    for (int nt = 0; nt < 2; nt++) {
        int c0 = nq * 16 + nt * 8 + 2 * tig;
        float m0 = 0.0f, m1 = 0.0f, m2 = 0.0f, m3 = 0.0f;
        #pragma unroll
        for (int b = 0; b < 3; b++) {
            float y0 = acc[b][nt][0], y1 = acc[b][nt][1];
            float y2 = acc[b][nt][2], y3 = acc[b][nt][3];
            m0 += y0; m1 += y1; m2 += y2; m3 += y3;
            *reinterpret_cast<float2*>(out_per + ((size_t)b * N + r0) * 64 + c0)
                = make_float2(sigmoidf_(y0), sigmoidf_(y1));
            *reinterpret_cast<float2*>(out_per + ((size_t)b * N + r1) * 64 + c0)
                = make_float2(sigmoidf_(y2), sigmoidf_(y3));
        }
        *reinterpret_cast<float2*>(out_mean + (size_t)r0 * 64 + c0)
            = make_float2(sigmoidf_(m0 * third), sigmoidf_(m1 * third));
        *reinterpret_cast<float2*>(out_mean + (size_t)r1 * 64 + c0)
            = make_float2(sigmoidf_(m2 * third), sigmoidf_(m3 * third));
    }
}

// ---------------------------------------------------------------------------
// Lazy stream/event creation (first call = correctness run, outside capture).
// ---------------------------------------------------------------------------
static cudaStream_t side_stream() {
    static cudaStream_t s = nullptr;
    if (!s) cudaStreamCreateWithFlags(&s, cudaStreamNonBlocking);
    return s;
}
static cudaEvent_t ev(int i) {
    static cudaEvent_t e[8] = {};
    if (!e[i]) cudaEventCreateWithFlags(&e[i], cudaEventDisableTiming);
    return e[i];
}

// ---------------------------------------------------------------------------
// Launch DAG (R11 scheme + W conversions on s1):
//   stream0: memset iscr[0] ─(wait cu)─ i2u[0] ─(waits)─ i2u[1,2]
//            ─(wait ui,mu)─ u2i x3 ─ fused dual gemm
//   s1:      convert_u ─ w32 convs ─ memset iscr[1,2] ─ memset uscr ─ convert_i
// ---------------------------------------------------------------------------
extern "C" void kernel_launch(void* const* d_in, const int* in_sizes, int n_in,
                              void* d_out, int out_size)
{
    const float* user_emb = (const float*)d_in[0];
    const float* item_emb = (const float*)d_in[1];
    const float* u2i_vals = (const float*)d_in[2];
    const int*   u2i_rows = (const int*)  d_in[3];
    const int*   u2i_cols = (const int*)  d_in[4];
    const float* i2u_vals = (const float*)d_in[5];
    const int*   i2u_rows = (const int*)  d_in[6];
    const int*   i2u_cols = (const int*)  d_in[7];
    const float* u_w      = (const float*)d_in[8];
    const float* i_w      = (const float*)d_in[9];

    float* out     = (float*)d_out;
    float* out_ue  = out;                                                 // [NU,64]
    float* out_ie  = out + (size_t)NU * DD;                               // [NI,64]
    float* out_ues = out + (size_t)(NU + NI) * DD;                        // [3,NU,64]
    float* out_ies = out + (size_t)(NU + NI) * DD + (size_t)BB * NU * DD; // [3,NI,64]

    void* p;
    cudaGetSymbolAddress(&p, g_uscr);     float*    uscr   = (float*)p;
    cudaGetSymbolAddress(&p, g_iscr);     float*    iscr   = (float*)p;
    cudaGetSymbolAddress(&p, g_emb16_u);  __half*   emb16u = (__half*)p;
    cudaGetSymbolAddress(&p, g_emb16_i);  __half*   emb16i = (__half*)p;
    cudaGetSymbolAddress(&p, g_w32_u);    uint32_t* w32u   = (uint32_t*)p;
    cudaGetSymbolAddress(&p, g_w32_i);    uint32_t* w32i   = (uint32_t*)p;

    cudaStream_t s1 = side_stream();
    cudaEvent_t e_fork = ev(0), e_cu = ev(1), e_s1 = ev(2), e_s2 = ev(3),
                e_mu = ev(4), e_ui = ev(5);

    const size_t ISLICE = (size_t)NI * DD * sizeof(float);

    cudaEventRecord(e_fork, 0);
    cudaStreamWaitEvent(s1, e_fork, 0);

    // s1: conversions + remaining memsets (all hidden under scatters)
    f32_to_f16<<<(NU * 16 + 255) / 256, 256, 0, s1>>>(
        (const float4*)user_emb, (__half2*)emb16u, NU * 16);
    cudaEventRecord(e_cu, s1);
    w_to_tf32<<<16, 256, 0, s1>>>(u_w, w32u);
    w_to_tf32<<<16, 256, 0, s1>>>(i_w, w32i);
    cudaMemsetAsync((char*)iscr + ISLICE, 0, ISLICE, s1);
    cudaEventRecord(e_s1, s1);
    cudaMemsetAsync((char*)iscr + 2 * ISLICE, 0, ISLICE, s1);
    cudaEventRecord(e_s2, s1);
    cudaMemsetAsync(uscr, 0, sizeof(g_uscr), s1);
    cudaEventRecord(e_mu, s1);
    f32_to_f16<<<(NI * 16 + 255) / 256, 256, 0, s1>>>(
        (const float4*)item_emb, (__half2*)emb16i, NI * 16);
    cudaEventRecord(e_ui, s1);

    // stream0: memset iscr slice 0 only
    cudaMemsetAsync(iscr, 0, ISLICE, 0);

    const int FULL_GRID = (EE + 255) / 256;

    cudaStreamWaitEvent(0, e_cu, 0);
    scatter_kernel<<<FULL_GRID, 256>>>(
        i2u_vals, i2u_rows, i2u_cols, emb16u, iscr, EE);
    cudaStreamWaitEvent(0, e_s1, 0);
    scatter_kernel<<<FULL_GRID, 256>>>(
        i2u_vals + (size_t)EE, i2u_rows + (size_t)EE, i2u_cols + (size_t)EE,
        emb16u, iscr + (size_t)NI * DD, EE);
    cudaStreamWaitEvent(0, e_s2, 0);
    scatter_kernel<<<FULL_GRID, 256>>>(
        i2u_vals + 2 * (size_t)EE, i2u_rows + 2 * (size_t)EE, i2u_cols + 2 * (size_t)EE,
        emb16u, iscr + 2 * (size_t)NI * DD, EE);

    cudaStreamWaitEvent(0, e_mu, 0);
    cudaStreamWaitEvent(0, e_ui, 0);
    for (int b = 0; b < BB; b++) {
        scatter_kernel<<<FULL_GRID, 256>>>(
            u2i_vals + (size_t)b * EE, u2i_rows + (size_t)b * EE,
            u2i_cols + (size_t)b * EE, emb16i,
            uscr + (size_t)b * NU * DD, EE);
    }

    // fused dual GEMM: both problems, one grid of 32-row tiles
    const int NBLK_U = NU / 32;
    const int NBLK_I = NI / 32;
    gemm_sig_mma_dual<<<NBLK_U + NBLK_I, 256>>>(
        uscr, w32u, out_ues, out_ue,
        iscr, w32i, out_ies, out_ie,
        NBLK_U);
}